// round 11
// baseline (speedup 1.0000x reference)
#include <cuda_runtime.h>
#include <cuda_fp16.h>
#include <math.h>

#define NN 100000
#define EE 1600000
#define DD 128
#define LL 3
#define EPSV 1e-5f
#define NCH ((NN + 1023) / 1024)   // scan chunks = 98

// ---------------- scratch (static __device__, no allocation) ----------------
__device__ int      g_is64;
__device__ int      g_deg[NN];
__device__ int      g_rowptr[NN + 1];
__device__ int      g_cursor[NN];
__device__ int      g_col[EE];
__device__ int      g_bsum[128];
__device__ int      g_boff[128];
__device__ float    g_invdeg[NN];
__device__ __half   g_hx[NN * DD];       // fp16 activations (raw pre-BN), in-place
__device__ __half   g_mh[NN * DD];       // fp16 neighbor mean
__device__ __half   g_wbh[2][128 * 256]; // folded fp16 weights, TRANSPOSED [n][k]
__device__ float    g_b2[2][DD];         // bias + sh^T Wr
__device__ float    g_cv[2][DD];         // sh^T Wl (applied x [deg>0])
__device__ float    g_sumS[2][DD];       // BN stat sums, double-slotted
__device__ float    g_sumsqS[2][DD];
__device__ float    g_p[NN];
__device__ float    g_q[NN];
__device__ unsigned g_barCnt;            // zero-initialized
__device__ unsigned g_barGen;

// ---------------- helpers ----------------
__device__ __forceinline__ void mma_f16(float* c, const unsigned* a, const unsigned* b) {
    asm volatile(
        "mma.sync.aligned.m16n8k16.row.col.f32.f16.f16.f32 "
        "{%0,%1,%2,%3}, {%4,%5,%6,%7}, {%8,%9}, {%0,%1,%2,%3};"
        : "+f"(c[0]), "+f"(c[1]), "+f"(c[2]), "+f"(c[3])
        : "r"(a[0]), "r"(a[1]), "r"(a[2]), "r"(a[3]), "r"(b[0]), "r"(b[1]));
}

__device__ __forceinline__ void cpa16(unsigned saddr, const void* g, int srcsz) {
    asm volatile("cp.async.cg.shared.global [%0], [%1], 16, %2;\n"
                 :: "r"(saddr), "l"(g), "r"(srcsz));
}
__device__ __forceinline__ void cpa_commit() {
    asm volatile("cp.async.commit_group;\n" ::: "memory");
}
template <int N> __device__ __forceinline__ void cpa_wait() {
    asm volatile("cp.async.wait_group %0;\n" :: "n"(N) : "memory");
}

__device__ __forceinline__ int dec_idx(const void* ei, long long pos, int is64) {
    int v = is64 ? (int)((const long long*)ei)[pos] : ((const int*)ei)[pos];
    return min(max(v, 0), NN - 1);
}

// sense-reversing grid barrier (all CTAs co-resident; sized via occupancy API)
__device__ __forceinline__ void grid_bar(int nb) {
    __syncthreads();
    if (threadIdx.x == 0) {
        __threadfence();                              // publish phase work
        unsigned gen = atomicAdd(&g_barGen, 0u);      // read BEFORE arriving
        unsigned arr = atomicAdd(&g_barCnt, 1u);
        if (arr == (unsigned)nb - 1u) {
            atomicExch(&g_barCnt, 0u);
            __threadfence();
            atomicAdd(&g_barGen, 1u);
        } else {
            while (atomicAdd(&g_barGen, 0u) == gen) { __nanosleep(64); }
        }
        __threadfence();
    }
    __syncthreads();
}

// ---------------- preamble kernels (unchanged structure) ----------------
__global__ void k_detect(const unsigned int* __restrict__ w) {
    __shared__ int nz;
    if (threadIdx.x == 0) nz = 0;
    __syncthreads();
    if (w[threadIdx.x * 2 + 1] != 0u) atomicOr(&nz, 1);
    __syncthreads();
    if (threadIdx.x == 0) g_is64 = nz ? 0 : 1;
}

__global__ void k_zero_deg() {
    int i = blockIdx.x * blockDim.x + threadIdx.x;
    if (i < NN) g_deg[i] = 0;
}

__global__ void k_hist(const void* __restrict__ ei) {
    int e = blockIdx.x * blockDim.x + threadIdx.x;
    if (e >= EE) return;
    int d = dec_idx(ei, (long long)EE + e, g_is64);
    atomicAdd(&g_deg[d], 1);
}

__global__ void k_scan_a() {
    __shared__ int swarp[32];
    int tid = threadIdx.x;
    int i = blockIdx.x * 1024 + tid;
    int v = (i < NN) ? g_deg[i] : 0;
    int lane = tid & 31, w = tid >> 5;
    int x = v;
    #pragma unroll
    for (int o = 1; o < 32; o <<= 1) {
        int y = __shfl_up_sync(0xffffffffu, x, o);
        if (lane >= o) x += y;
    }
    if (lane == 31) swarp[w] = x;
    __syncthreads();
    if (w == 0) {
        int y = swarp[lane];
        #pragma unroll
        for (int o = 1; o < 32; o <<= 1) {
            int z = __shfl_up_sync(0xffffffffu, y, o);
            if (lane >= o) y += z;
        }
        swarp[lane] = y;
    }
    __syncthreads();
    int add = (w > 0) ? swarp[w - 1] : 0;
    x += add;
    if (i < NN) g_rowptr[i + 1] = x;
    if (tid == 1023) g_bsum[blockIdx.x] = x;
}

__global__ void k_scan_b() {
    if (threadIdx.x == 0) {
        int r = 0;
        for (int b = 0; b < NCH; b++) { g_boff[b] = r; r += g_bsum[b]; }
    }
}

__global__ void k_scan_c() {
    int i = blockIdx.x * blockDim.x + threadIdx.x;
    if (i < NN) {
        g_rowptr[i + 1] += g_boff[i >> 10];
        if (i == 0) g_rowptr[0] = 0;
    }
}

__global__ void k_prep() {
    int i = blockIdx.x * blockDim.x + threadIdx.x;
    if (i < NN) {
        g_cursor[i] = g_rowptr[i];
        int d = g_deg[i];
        g_invdeg[i] = (d > 0) ? (1.0f / (float)d) : 0.0f;
    }
}

__global__ void k_scatter(const void* __restrict__ ei) {
    int e = blockIdx.x * blockDim.x + threadIdx.x;
    if (e < EE) {
        int is64 = g_is64;
        int s = dec_idx(ei, e, is64);
        int d = dec_idx(ei, (long long)EE + e, is64);
        int pos = atomicAdd(&g_cursor[d], 1);
        g_col[pos] = s;
    }
}

__global__ void k_x2h(const float* __restrict__ x) {
    int i4 = blockIdx.x * blockDim.x + threadIdx.x;   // float4 index
    if (i4 < NN * (DD / 4)) {
        float4 v = __ldg(&((const float4*)x)[i4]);
        __half2 h0 = __floats2half2_rn(v.x, v.y);
        __half2 h1 = __floats2half2_rn(v.z, v.w);
        uint2 o;
        o.x = *(unsigned*)&h0;
        o.y = *(unsigned*)&h1;
        ((uint2*)g_hx)[i4] = o;
    }
}

// layer-0 weight fold (no BN): Wt[n][k] = fp16([Wl;Wr][k][n]); zero stat slot 0
__global__ void k_wprep0(const float* __restrict__ Wl, const float* __restrict__ Wr,
                         const float* __restrict__ bias) {
    int blk = blockIdx.x, j = threadIdx.x;
    if (blk < 256) {
        int k = blk & 127;
        const float* W = (blk < 128) ? Wl : Wr;
        g_wbh[0][j * 256 + blk] = __float2half(__ldg(&W[k * DD + j]));
    } else {
        g_b2[0][j] = __ldg(&bias[j]);
        g_cv[0][j] = 0.0f;
        g_sumS[0][j] = 0.0f;
        g_sumsqS[0][j] = 0.0f;
    }
}

// ---------------- mma tile (R8-proven body, __ldcg cross-phase reads) -------
#define SAKH 40
#define BUF_BYTES (128 * SAKH * 2 * 2)      // A (10240) + W (10240) = 20480
#define SMEM_MMA (2 * BUF_BYTES)            // 40960 B

__device__ __forceinline__ void mma_tile(
    int rowBase, const __half* wbuf, const float* bias2, const float* cvec,
    float* sumOut, float* sumsqOut, __half* smh, unsigned smbase)
{
    int tid = threadIdx.x;
    int wid = tid >> 5;
    int lane = tid & 31;
    int wr_ = wid >> 2;
    int wc = wid & 3;
    int g = lane >> 2;
    int t = lane & 3;

    float acc[4][4][4];
    #pragma unroll
    for (int mt = 0; mt < 4; mt++)
        #pragma unroll
        for (int nt = 0; nt < 4; nt++)
            #pragma unroll
            for (int q = 0; q < 4; q++) acc[mt][nt][q] = 0.0f;

    auto stage = [&](int ck, int b) {
        unsigned base = smbase + (unsigned)b * BUF_BYTES;
        #pragma unroll
        for (int it = 0; it < 4; it++) {
            int i = tid + it * 256;          // 0..1023
            if (i < 512) {                   // A: 128 rows x 4 segs of 16B
                int r = i >> 2, seg = i & 3;
                int row = rowBase + r;
                int ok = (row < NN) ? 16 : 0;
                int crow = min(row, NN - 1);
                const __half* gp = (ck < 4)
                    ? (g_mh + (size_t)crow * DD + ck * 32 + seg * 8)
                    : (g_hx + (size_t)crow * DD + (ck - 4) * 32 + seg * 8);
                cpa16(base + (unsigned)(r * SAKH + seg * 8) * 2u, gp, ok);
            } else {                         // W: 128 n-rows x 4 segs of 16B
                int i2 = i - 512;
                int r = i2 >> 2, seg = i2 & 3;
                const __half* gp = wbuf + (size_t)r * 256 + ck * 32 + seg * 8;
                cpa16(base + (unsigned)(128 * SAKH + r * SAKH + seg * 8) * 2u, gp, 16);
            }
        }
    };

    stage(0, 0);
    cpa_commit();

    #pragma unroll 1
    for (int ck = 0; ck < 8; ck++) {
        if (ck < 7) {
            stage(ck + 1, (ck + 1) & 1);   // issue next stage BEFORE waiting
            cpa_commit();
            cpa_wait<1>();
        } else {
            cpa_wait<0>();
        }
        __syncthreads();

        const __half* bA = smh + (ck & 1) * (BUF_BYTES / 2);
        const __half* bW = bA + 128 * SAKH;

        #pragma unroll
        for (int kk = 0; kk < 2; kk++) {
            unsigned a[4][4];
            #pragma unroll
            for (int mt = 0; mt < 4; mt++) {
                const __half* pa = bA + (wr_ * 64 + mt * 16 + g) * SAKH + kk * 16 + 2 * t;
                a[mt][0] = *(const unsigned*)(pa);
                a[mt][1] = *(const unsigned*)(pa + 8 * SAKH);
                a[mt][2] = *(const unsigned*)(pa + 8);
                a[mt][3] = *(const unsigned*)(pa + 8 * SAKH + 8);
            }
            unsigned b[4][2];
            #pragma unroll
            for (int nt = 0; nt < 4; nt++) {
                const __half* pb = bW + (wc * 32 + nt * 8 + g) * SAKH + kk * 16 + 2 * t;
                b[nt][0] = *(const unsigned*)(pb);
                b[nt][1] = *(const unsigned*)(pb + 8);
            }
            #pragma unroll
            for (int mt = 0; mt < 4; mt++)
                #pragma unroll
                for (int nt = 0; nt < 4; nt++)
                    mma_f16(acc[mt][nt], a[mt], b[nt]);
        }
        __syncthreads();
    }

    // epilogue: bias' + flag*cvec + relu + fp16 in-place store + stats
    float b20[4], b21[4], cv0[4], cv1[4];
    #pragma unroll
    for (int nt = 0; nt < 4; nt++) {
        int cb = wc * 32 + nt * 8 + t * 2;
        b20[nt] = __ldcg(&bias2[cb]);
        b21[nt] = __ldcg(&bias2[cb + 1]);
        cv0[nt] = __ldcg(&cvec[cb]);
        cv1[nt] = __ldcg(&cvec[cb + 1]);
    }

    float cs[8], cq[8];
    #pragma unroll
    for (int q = 0; q < 8; q++) { cs[q] = 0.f; cq[q] = 0.f; }

    #pragma unroll
    for (int mt = 0; mt < 4; mt++) {
        int r0 = rowBase + wr_ * 64 + mt * 16 + g;
        int r1 = r0 + 8;
        float f0 = (r0 < NN && __ldg(&g_invdeg[r0]) > 0.0f) ? 1.0f : 0.0f;
        float f1 = (r1 < NN && __ldg(&g_invdeg[r1]) > 0.0f) ? 1.0f : 0.0f;
        #pragma unroll
        for (int nt = 0; nt < 4; nt++) {
            int cb = wc * 32 + nt * 8 + t * 2;
            float v0 = fmaxf(acc[mt][nt][0] + b20[nt] + f0 * cv0[nt], 0.0f);
            float v1 = fmaxf(acc[mt][nt][1] + b21[nt] + f0 * cv1[nt], 0.0f);
            float v2 = fmaxf(acc[mt][nt][2] + b20[nt] + f1 * cv0[nt], 0.0f);
            float v3 = fmaxf(acc[mt][nt][3] + b21[nt] + f1 * cv1[nt], 0.0f);
            if (r0 < NN) {
                __half2 hh = __floats2half2_rn(v0, v1);
                *(unsigned*)(g_hx + (size_t)r0 * DD + cb) = *(unsigned*)&hh;
                cs[nt * 2] += v0;     cq[nt * 2] += v0 * v0;
                cs[nt * 2 + 1] += v1; cq[nt * 2 + 1] += v1 * v1;
            }
            if (r1 < NN) {
                __half2 hh = __floats2half2_rn(v2, v3);
                *(unsigned*)(g_hx + (size_t)r1 * DD + cb) = *(unsigned*)&hh;
                cs[nt * 2] += v2;     cq[nt * 2] += v2 * v2;
                cs[nt * 2 + 1] += v3; cq[nt * 2 + 1] += v3 * v3;
            }
        }
    }

    __syncthreads();
    float* smf = (float*)smh;
    if (tid < 256) smf[tid] = 0.0f;
    __syncthreads();
    #pragma unroll
    for (int nt = 0; nt < 4; nt++) {
        int cb = wc * 32 + nt * 8 + t * 2;
        atomicAdd(&smf[cb], cs[nt * 2]);
        atomicAdd(&smf[cb + 1], cs[nt * 2 + 1]);
        atomicAdd(&smf[128 + cb], cq[nt * 2]);
        atomicAdd(&smf[128 + cb + 1], cq[nt * 2 + 1]);
    }
    __syncthreads();
    if (tid < 128) {
        atomicAdd(&sumOut[tid], smf[tid]);
        atomicAdd(&sumsqOut[tid], smf[128 + tid]);
    }
    __syncthreads();   // protect smf before next tile's stage reuses smem
}

// ---------------- the persistent mega kernel --------------------------------
__global__ void __launch_bounds__(256, 2) k_mega(
    const float* __restrict__ Wl, const float* __restrict__ Wr,
    const float* __restrict__ bias,
    const float* __restrict__ gamma, const float* __restrict__ beta,
    const float* __restrict__ wlo, const float* __restrict__ wro,
    const float* __restrict__ b_out, float* __restrict__ out)
{
    extern __shared__ __half smh[];
    unsigned smbase = (unsigned)__cvta_generic_to_shared(smh);
    const int nb = gridDim.x;
    const int tid = threadIdx.x;
    const int lane = tid & 31;
    const int nWarps = nb * 8;
    const int gw = blockIdx.x * 8 + (tid >> 5);
    const int nTiles = (NN + 127) / 128;
    const float inv = 1.0f / (float)NN;

    for (int l = 0; l < LL; l++) {
        int slot = l & 1;

        // ---- phase A: aggregation over all nodes (+ weight fold for l>0) ---
        for (int n = gw; n < NN; n += nWarps) {
            int s = g_rowptr[n], e = g_rowptr[n + 1];
            float4 acc = make_float4(0.f, 0.f, 0.f, 0.f);
            const __half* hx = g_hx;
            int j = s;
            for (; j + 3 < e; j += 4) {
                int c0 = g_col[j], c1 = g_col[j + 1], c2 = g_col[j + 2], c3 = g_col[j + 3];
                uint2 a = __ldcg(((const uint2*)(hx + (size_t)c0 * DD)) + lane);
                uint2 b = __ldcg(((const uint2*)(hx + (size_t)c1 * DD)) + lane);
                uint2 c = __ldcg(((const uint2*)(hx + (size_t)c2 * DD)) + lane);
                uint2 d = __ldcg(((const uint2*)(hx + (size_t)c3 * DD)) + lane);
                float2 a0 = __half22float2(*(__half2*)&a.x), a1 = __half22float2(*(__half2*)&a.y);
                float2 b0 = __half22float2(*(__half2*)&b.x), b1 = __half22float2(*(__half2*)&b.y);
                float2 c0f = __half22float2(*(__half2*)&c.x), c1f = __half22float2(*(__half2*)&c.y);
                float2 d0 = __half22float2(*(__half2*)&d.x), d1 = __half22float2(*(__half2*)&d.y);
                acc.x += (a0.x + b0.x) + (c0f.x + d0.x);
                acc.y += (a0.y + b0.y) + (c0f.y + d0.y);
                acc.z += (a1.x + b1.x) + (c1f.x + d1.x);
                acc.w += (a1.y + b1.y) + (c1f.y + d1.y);
            }
            for (; j < e; j++) {
                uint2 a = __ldcg(((const uint2*)(hx + (size_t)g_col[j] * DD)) + lane);
                float2 a0 = __half22float2(*(__half2*)&a.x), a1 = __half22float2(*(__half2*)&a.y);
                acc.x += a0.x; acc.y += a0.y; acc.z += a1.x; acc.w += a1.y;
            }
            float iv = __ldg(&g_invdeg[n]);
            __half2 h0 = __floats2half2_rn(acc.x * iv, acc.y * iv);
            __half2 h1 = __floats2half2_rn(acc.z * iv, acc.w * iv);
            uint2 o;
            o.x = *(unsigned*)&h0;
            o.y = *(unsigned*)&h1;
            ((uint2*)(g_mh + (size_t)n * DD))[lane] = o;
        }

        if (l > 0) {
            int ps = 1 - slot;
            const float* WlL = Wl + (size_t)l * DD * DD;
            const float* WrL = Wr + (size_t)l * DD * DD;
            const float* gmP = gamma + (l - 1) * DD;
            const float* btP = beta + (l - 1) * DD;
            // fold weight elements
            int gt = blockIdx.x * 256 + tid;
            int gs = nb * 256;
            for (int idx = gt; idx < 256 * DD; idx += gs) {
                int kk2 = idx >> 7;      // 0..255
                int j = idx & 127;
                int k = kk2 & 127;
                float m = __ldcg(&g_sumS[ps][k]) * inv;
                float v = fmaxf(__ldcg(&g_sumsqS[ps][k]) * inv - m * m, 0.0f);
                float s = __ldg(&gmP[k]) * rsqrtf(v + EPSV);
                const float* W = (kk2 < 128) ? WlL : WrL;
                g_wbh[slot][j * 256 + kk2] = __float2half(s * __ldg(&W[k * DD + j]));
            }
            // b2 / cv: warp per output column
            if (gw < DD) {
                int j = gw;
                float sb = 0.0f, sc = 0.0f;
                for (int k = lane; k < DD; k += 32) {
                    float m = __ldcg(&g_sumS[ps][k]) * inv;
                    float v = fmaxf(__ldcg(&g_sumsqS[ps][k]) * inv - m * m, 0.0f);
                    float s = __ldg(&gmP[k]) * rsqrtf(v + EPSV);
                    float sh = __ldg(&btP[k]) - m * s;
                    sc += sh * __ldg(&WlL[k * DD + j]);
                    sb += sh * __ldg(&WrL[k * DD + j]);
                }
                #pragma unroll
                for (int o = 16; o > 0; o >>= 1) {
                    sb += __shfl_down_sync(0xffffffffu, sb, o);
                    sc += __shfl_down_sync(0xffffffffu, sc, o);
                }
                if (lane == 0) {
                    g_b2[slot][j] = __ldg(&bias[l * DD + j]) + sb;
                    g_cv[slot][j] = sc;
                }
            }
            // zero this layer's stat slot
            if (blockIdx.x == nb - 1 && tid < DD) {
                g_sumS[slot][tid] = 0.0f;
                g_sumsqS[slot][tid] = 0.0f;
            }
        }
        grid_bar(nb);

        // ---- phase B: mma over row tiles ----
        for (int tile = blockIdx.x; tile < nTiles; tile += nb) {
            mma_tile(tile * 128, g_wbh[slot], g_b2[slot], g_cv[slot],
                     g_sumS[slot], g_sumsqS[slot], smh, smbase);
        }
        grid_bar(nb);
    }

    // ---- pq phase (last BN computed inline) ----
    {
        int slot = (LL - 1) & 1;
        const float* gmL = gamma + (LL - 1) * DD;
        const float* btL = beta + (LL - 1) * DD;
        float sc4[4], sh4[4];
        #pragma unroll
        for (int q2 = 0; q2 < 4; q2++) {
            int c = lane * 4 + q2;
            float m = __ldcg(&g_sumS[slot][c]) * inv;
            float v = fmaxf(__ldcg(&g_sumsqS[slot][c]) * inv - m * m, 0.0f);
            float s = __ldg(&gmL[c]) * rsqrtf(v + EPSV);
            sc4[q2] = s;
            sh4[q2] = __ldg(&btL[c]) - m * s;
        }
        float4 wl = __ldg(&((const float4*)wlo)[lane]);
        float4 wrv = __ldg(&((const float4*)wro)[lane]);
        for (int n = gw; n < NN; n += nWarps) {
            uint2 hraw = __ldcg(((const uint2*)(g_hx + (size_t)n * DD)) + lane);
            float2 v0 = __half22float2(*(__half2*)&hraw.x);
            float2 v1 = __half22float2(*(__half2*)&hraw.y);
            float hx0 = sc4[0] * v0.x + sh4[0];
            float hx1 = sc4[1] * v0.y + sh4[1];
            float hx2 = sc4[2] * v1.x + sh4[2];
            float hx3 = sc4[3] * v1.y + sh4[3];
            float p = hx0 * wl.x + hx1 * wl.y + hx2 * wl.z + hx3 * wl.w;
            float q = hx0 * wrv.x + hx1 * wrv.y + hx2 * wrv.z + hx3 * wrv.w;
            #pragma unroll
            for (int o = 16; o > 0; o >>= 1) {
                p += __shfl_down_sync(0xffffffffu, p, o);
                q += __shfl_down_sync(0xffffffffu, q, o);
            }
            if (lane == 0) { g_p[n] = p; g_q[n] = q; }
        }
    }
    grid_bar(nb);

    // ---- final phase ----
    {
        float bo0 = __ldg(&b_out[0]);
        for (int n = blockIdx.x * 256 + tid; n < NN; n += nb * 256) {
            int s = g_rowptr[n], e = g_rowptr[n + 1];
            float acc = 0.0f;
            for (int j = s; j < e; j++) acc += __ldcg(&g_p[g_col[j]]);
            float z = acc * __ldg(&g_invdeg[n]) + __ldcg(&g_q[n]) + bo0;
            out[n] = 1.0f / (1.0f + expf(-z));
        }
    }
}

// ---------------- host ----------------
extern "C" void kernel_launch(void* const* d_in, const int* in_sizes, int n_in,
                              void* d_out, int out_size) {
    const float* x     = (const float*)d_in[0];
    const void*  ei    = d_in[1];
    const float* Wl    = (const float*)d_in[2];
    const float* Wr    = (const float*)d_in[3];
    const float* b     = (const float*)d_in[4];
    const float* gamma = (const float*)d_in[5];
    const float* beta  = (const float*)d_in[6];
    const float* Wlo   = (const float*)d_in[7];
    const float* Wro   = (const float*)d_in[8];
    const float* bo    = (const float*)d_in[9];
    float* out = (float*)d_out;

    cudaFuncSetAttribute(k_mega, cudaFuncAttributeMaxDynamicSharedMemorySize, SMEM_MMA);

    // co-resident grid sizing (host-side queries; capture-safe)
    int dev = 0;
    cudaGetDevice(&dev);
    int sms = 0;
    cudaDeviceGetAttribute(&sms, cudaDevAttrMultiProcessorCount, dev);
    int nbk = 0;
    cudaOccupancyMaxActiveBlocksPerMultiprocessor(&nbk, k_mega, 256, SMEM_MMA);
    if (nbk < 1) nbk = 1;
    if (nbk > 2) nbk = 2;
    int grid = sms * nbk;

    // preamble: detect, zero deg, hist, x2h, layer-0 fold, CSR scan + scatter
    k_detect<<<1, 256>>>((const unsigned int*)ei);
    k_zero_deg<<<(NN + 255) / 256, 256>>>();
    k_hist<<<(EE + 255) / 256, 256>>>(ei);
    k_x2h<<<(NN * (DD / 4) + 255) / 256, 256>>>(x);
    k_wprep0<<<257, 128>>>(Wl, Wr, b);
    k_scan_a<<<NCH, 1024>>>();
    k_scan_b<<<1, 32>>>();
    k_scan_c<<<(NN + 255) / 256, 256>>>();
    k_prep<<<(NN + 255) / 256, 256>>>();
    k_scatter<<<(EE + 255) / 256, 256>>>(ei);

    // the whole layered pipeline in one persistent kernel
    k_mega<<<grid, 256, SMEM_MMA>>>(Wl, Wr, b, gamma, beta, Wlo, Wro, bo, out);

    (void)in_sizes; (void)n_in; (void)out_size;
}

// round 12
// speedup vs baseline: 1.2105x; 1.2105x over previous
#include <cuda_runtime.h>
#include <cuda_fp16.h>
#include <math.h>

#define NN 100000
#define EE 1600000
#define DD 128
#define LL 3
#define EPSV 1e-5f
#define NCH ((NN + 1023) / 1024)   // scan chunks = 98

// ---------------- scratch (static __device__, no allocation) ----------------
__device__ int    g_is64;
__device__ int    g_deg[NN];
__device__ int    g_rowptr[NN + 1];
__device__ int    g_cursor[NN];
__device__ int    g_col[EE];
__device__ int    g_bsum[128];
__device__ int    g_boff[128];
__device__ float  g_invdeg[NN];
__device__ __half g_hx[NN * DD];       // fp16 activations (raw pre-BN), in-place
__device__ __half g_mh[NN * DD];       // fp16 neighbor mean
__device__ __half g_wbh[2][128 * 256]; // folded fp16 weights, TRANSPOSED [n][k]
__device__ float  g_b2[2][DD];         // bias + sh^T Wr
__device__ float  g_cv[2][DD];         // sh^T Wl (applied x [deg>0])
__device__ float  g_sum[DD];
__device__ float  g_sumsq[DD];
__device__ float  g_scale[DD];
__device__ float  g_shift[DD];
__device__ float  g_p[NN];
__device__ float  g_q[NN];

// ---------------- helpers ----------------
__device__ __forceinline__ void mma_f16(float* c, const unsigned* a, const unsigned* b) {
    asm volatile(
        "mma.sync.aligned.m16n8k16.row.col.f32.f16.f16.f32 "
        "{%0,%1,%2,%3}, {%4,%5,%6,%7}, {%8,%9}, {%0,%1,%2,%3};"
        : "+f"(c[0]), "+f"(c[1]), "+f"(c[2]), "+f"(c[3])
        : "r"(a[0]), "r"(a[1]), "r"(a[2]), "r"(a[3]), "r"(b[0]), "r"(b[1]));
}

__device__ __forceinline__ void cpa16(unsigned saddr, const void* g, int srcsz) {
    asm volatile("cp.async.cg.shared.global [%0], [%1], 16, %2;\n"
                 :: "r"(saddr), "l"(g), "r"(srcsz));
}
__device__ __forceinline__ void cpa_commit() {
    asm volatile("cp.async.commit_group;\n" ::: "memory");
}
template <int N> __device__ __forceinline__ void cpa_wait() {
    asm volatile("cp.async.wait_group %0;\n" :: "n"(N) : "memory");
}

__device__ __forceinline__ int dec_idx(const void* ei, long long pos, int is64) {
    int v = is64 ? (int)((const long long*)ei)[pos] : ((const int*)ei)[pos];
    return min(max(v, 0), NN - 1);
}

// ---------------- dtype detect ----------------
__global__ void k_detect(const unsigned int* __restrict__ w) {
    __shared__ int nz;
    if (threadIdx.x == 0) nz = 0;
    __syncthreads();
    if (w[threadIdx.x * 2 + 1] != 0u) atomicOr(&nz, 1);
    __syncthreads();
    if (threadIdx.x == 0) g_is64 = nz ? 0 : 1;
}

__global__ void k_zero_deg() {
    int i = blockIdx.x * blockDim.x + threadIdx.x;
    if (i < NN) g_deg[i] = 0;
}

__global__ void k_hist(const void* __restrict__ ei) {
    int e = blockIdx.x * blockDim.x + threadIdx.x;
    if (e >= EE) return;
    int d = dec_idx(ei, (long long)EE + e, g_is64);
    atomicAdd(&g_deg[d], 1);
}

// ---------------- CSR scan ----------------
__global__ void k_scan_a() {
    __shared__ int swarp[32];
    int tid = threadIdx.x;
    int i = blockIdx.x * 1024 + tid;
    int v = (i < NN) ? g_deg[i] : 0;
    int lane = tid & 31, w = tid >> 5;
    int x = v;
    #pragma unroll
    for (int o = 1; o < 32; o <<= 1) {
        int y = __shfl_up_sync(0xffffffffu, x, o);
        if (lane >= o) x += y;
    }
    if (lane == 31) swarp[w] = x;
    __syncthreads();
    if (w == 0) {
        int y = swarp[lane];
        #pragma unroll
        for (int o = 1; o < 32; o <<= 1) {
            int z = __shfl_up_sync(0xffffffffu, y, o);
            if (lane >= o) y += z;
        }
        swarp[lane] = y;
    }
    __syncthreads();
    int add = (w > 0) ? swarp[w - 1] : 0;
    x += add;
    if (i < NN) g_rowptr[i + 1] = x;
    if (tid == 1023) g_bsum[blockIdx.x] = x;
}

__global__ void k_scan_b() {
    if (threadIdx.x == 0) {
        int r = 0;
        for (int b = 0; b < NCH; b++) { g_boff[b] = r; r += g_bsum[b]; }
    }
}

__global__ void k_scan_c() {
    int i = blockIdx.x * blockDim.x + threadIdx.x;
    if (i < NN) {
        g_rowptr[i + 1] += g_boff[i >> 10];
        if (i == 0) g_rowptr[0] = 0;
    }
}

// prep + zero first-layer BN stats
__global__ void k_prep() {
    int i = blockIdx.x * blockDim.x + threadIdx.x;
    if (i < NN) {
        g_cursor[i] = g_rowptr[i];
        int d = g_deg[i];
        g_invdeg[i] = (d > 0) ? (1.0f / (float)d) : 0.0f;
    }
    if (i < DD) { g_sum[i] = 0.0f; g_sumsq[i] = 0.0f; }
}

__global__ void k_scatter(const void* __restrict__ ei) {
    int e = blockIdx.x * blockDim.x + threadIdx.x;
    if (e < EE) {
        int is64 = g_is64;
        int s = dec_idx(ei, e, is64);
        int d = dec_idx(ei, (long long)EE + e, is64);
        int pos = atomicAdd(&g_cursor[d], 1);
        g_col[pos] = s;
    }
}

// ---------------- x -> fp16 mirror ----------------
__global__ void k_x2h(const float* __restrict__ x) {
    int i4 = blockIdx.x * blockDim.x + threadIdx.x;   // float4 index
    if (i4 < NN * (DD / 4)) {
        float4 v = __ldg(&((const float4*)x)[i4]);
        __half2 h0 = __floats2half2_rn(v.x, v.y);
        __half2 h1 = __floats2half2_rn(v.z, v.w);
        uint2 o;
        o.x = *(unsigned*)&h0;
        o.y = *(unsigned*)&h1;
        ((uint2*)g_hx)[i4] = o;
    }
}

// --------- weight fold: Wt[n][k] = fp16(s_k * [Wl;Wr][k][n]), bias', cvec ---
__global__ void k_wprep(const float* __restrict__ Wl, const float* __restrict__ Wr,
                        const float* __restrict__ bias, int useScale,
                        __half* __restrict__ wout, float* __restrict__ b2,
                        float* __restrict__ cv) {
    int blk = blockIdx.x, j = threadIdx.x;   // j = n (output col)
    if (blk < 256) {
        int k = (blk < 128) ? blk : blk - 128;
        float s = useScale ? g_scale[k] : 1.0f;
        const float* W = (blk < 128) ? Wl : Wr;
        wout[j * 256 + blk] = __float2half(s * __ldg(&W[k * DD + j]));
    } else {
        float sb = 0.0f, sc = 0.0f;
        if (useScale) {
            for (int k = 0; k < DD; k++) {
                float sh = g_shift[k];
                sc += sh * __ldg(&Wl[k * DD + j]);
                sb += sh * __ldg(&Wr[k * DD + j]);
            }
        }
        b2[j] = __ldg(&bias[j]) + sb;
        cv[j] = sc;
    }
}

// ------- aggregation: warp per node, fp16 gather, fp32 acc, fp16 store ------
__global__ void __launch_bounds__(256) k_agg() {
    int n = blockIdx.x * 8 + (threadIdx.x >> 5);
    if (n >= NN) return;
    int lane = threadIdx.x & 31;
    int s = g_rowptr[n], e = g_rowptr[n + 1];
    float4 acc = make_float4(0.f, 0.f, 0.f, 0.f);
    const __half* hx = g_hx;
    int j = s;
    for (; j + 3 < e; j += 4) {
        int c0 = g_col[j], c1 = g_col[j + 1], c2 = g_col[j + 2], c3 = g_col[j + 3];
        uint2 a = __ldg(((const uint2*)(hx + (size_t)c0 * DD)) + lane);
        uint2 b = __ldg(((const uint2*)(hx + (size_t)c1 * DD)) + lane);
        uint2 c = __ldg(((const uint2*)(hx + (size_t)c2 * DD)) + lane);
        uint2 d = __ldg(((const uint2*)(hx + (size_t)c3 * DD)) + lane);
        float2 a0 = __half22float2(*(__half2*)&a.x), a1 = __half22float2(*(__half2*)&a.y);
        float2 b0 = __half22float2(*(__half2*)&b.x), b1 = __half22float2(*(__half2*)&b.y);
        float2 c0f = __half22float2(*(__half2*)&c.x), c1f = __half22float2(*(__half2*)&c.y);
        float2 d0 = __half22float2(*(__half2*)&d.x), d1 = __half22float2(*(__half2*)&d.y);
        acc.x += (a0.x + b0.x) + (c0f.x + d0.x);
        acc.y += (a0.y + b0.y) + (c0f.y + d0.y);
        acc.z += (a1.x + b1.x) + (c1f.x + d1.x);
        acc.w += (a1.y + b1.y) + (c1f.y + d1.y);
    }
    for (; j < e; j++) {
        uint2 a = __ldg(((const uint2*)(hx + (size_t)g_col[j] * DD)) + lane);
        float2 a0 = __half22float2(*(__half2*)&a.x), a1 = __half22float2(*(__half2*)&a.y);
        acc.x += a0.x; acc.y += a0.y; acc.z += a1.x; acc.w += a1.y;
    }
    float iv = g_invdeg[n];
    __half2 h0 = __floats2half2_rn(acc.x * iv, acc.y * iv);
    __half2 h1 = __floats2half2_rn(acc.z * iv, acc.w * iv);
    uint2 o;
    o.x = *(unsigned*)&h0;
    o.y = *(unsigned*)&h1;
    ((uint2*)(g_mh + (size_t)n * DD))[lane] = o;
}

// ---------------- fp16 MMA, cp.async double-buffered ------------------------
// C = [mean | root] (K=256) @ foldedW, + bias' + flag*cvec, relu, stats.
// BK=32, 8 chunks. A smem [128 rows][40 halves pad], W smem [128 n][40 halves].
// m16n8k16 fp16 mma, fp32 accum. In-place g_hx epilogue (own rows only).
#define SAKH 40
#define BUF_BYTES (128 * SAKH * 2 * 2)      // A (10240) + W (10240) = 20480
#define SMEM_MMA (2 * BUF_BYTES)            // 40960 B

__global__ void __launch_bounds__(256, 2) k_mma(
    const __half* __restrict__ wbuf, const float* __restrict__ bias2,
    const float* __restrict__ cvec)
{
    extern __shared__ __half smh[];
    unsigned smbase = (unsigned)__cvta_generic_to_shared(smh);

    int tid = threadIdx.x;
    int wid = tid >> 5;
    int lane = tid & 31;
    int wr_ = wid >> 2;
    int wc = wid & 3;
    int g = lane >> 2;
    int t = lane & 3;
    int rowBase = blockIdx.x * 128;

    float acc[4][4][4];
    #pragma unroll
    for (int mt = 0; mt < 4; mt++)
        #pragma unroll
        for (int nt = 0; nt < 4; nt++)
            #pragma unroll
            for (int q = 0; q < 4; q++) acc[mt][nt][q] = 0.0f;

    // stage chunk ck into buffer b: A rows from mean/root fp16, W from wbuf
    auto stage = [&](int ck, int b) {
        unsigned base = smbase + b * BUF_BYTES;
        #pragma unroll
        for (int it = 0; it < 4; it++) {
            int i = tid + it * 256;          // 0..1023
            if (i < 512) {                   // A: 128 rows x 4 segs of 16B
                int r = i >> 2, seg = i & 3;
                int row = rowBase + r;
                int ok = (row < NN) ? 16 : 0;
                int crow = min(row, NN - 1);
                const __half* gp = (ck < 4)
                    ? (g_mh + (size_t)crow * DD + ck * 32 + seg * 8)
                    : (g_hx + (size_t)crow * DD + (ck - 4) * 32 + seg * 8);
                cpa16(base + (unsigned)(r * SAKH + seg * 8) * 2u, gp, ok);
            } else {                         // W: 128 n-rows x 4 segs of 16B
                int i2 = i - 512;
                int r = i2 >> 2, seg = i2 & 3;
                const __half* gp = wbuf + (size_t)r * 256 + ck * 32 + seg * 8;
                cpa16(base + (unsigned)(128 * SAKH + r * SAKH + seg * 8) * 2u, gp, 16);
            }
        }
    };

    stage(0, 0);
    cpa_commit();

    #pragma unroll 1
    for (int ck = 0; ck < 8; ck++) {
        if (ck < 7) {
            stage(ck + 1, (ck + 1) & 1);
            cpa_commit();
            cpa_wait<1>();
        } else {
            cpa_wait<0>();
        }
        __syncthreads();

        const __half* bA = smh + (ck & 1) * (BUF_BYTES / 2);
        const __half* bW = bA + 128 * SAKH;

        #pragma unroll
        for (int kk = 0; kk < 2; kk++) {     // two k16 steps cover BK=32
            unsigned a[4][4];
            #pragma unroll
            for (int mt = 0; mt < 4; mt++) {
                const __half* pa = bA + (wr_ * 64 + mt * 16 + g) * SAKH + kk * 16 + 2 * t;
                a[mt][0] = *(const unsigned*)(pa);
                a[mt][1] = *(const unsigned*)(pa + 8 * SAKH);
                a[mt][2] = *(const unsigned*)(pa + 8);
                a[mt][3] = *(const unsigned*)(pa + 8 * SAKH + 8);
            }
            unsigned b[4][2];
            #pragma unroll
            for (int nt = 0; nt < 4; nt++) {
                const __half* pb = bW + (wc * 32 + nt * 8 + g) * SAKH + kk * 16 + 2 * t;
                b[nt][0] = *(const unsigned*)(pb);
                b[nt][1] = *(const unsigned*)(pb + 8);
            }
            #pragma unroll
            for (int mt = 0; mt < 4; mt++)
                #pragma unroll
                for (int nt = 0; nt < 4; nt++)
                    mma_f16(acc[mt][nt], a[mt], b[nt]);
        }
        __syncthreads();
    }

    // ---- epilogue: bias' + flag*cvec + relu + fp16 store (in-place) + stats
    float b20[4], b21[4], cv0[4], cv1[4];
    #pragma unroll
    for (int nt = 0; nt < 4; nt++) {
        int cb = wc * 32 + nt * 8 + t * 2;
        b20[nt] = __ldg(&bias2[cb]);
        b21[nt] = __ldg(&bias2[cb + 1]);
        cv0[nt] = __ldg(&cvec[cb]);
        cv1[nt] = __ldg(&cvec[cb + 1]);
    }

    float cs[8], cq[8];
    #pragma unroll
    for (int q = 0; q < 8; q++) { cs[q] = 0.f; cq[q] = 0.f; }

    #pragma unroll
    for (int mt = 0; mt < 4; mt++) {
        int r0 = rowBase + wr_ * 64 + mt * 16 + g;
        int r1 = r0 + 8;
        float f0 = (r0 < NN && g_invdeg[r0] > 0.0f) ? 1.0f : 0.0f;
        float f1 = (r1 < NN && g_invdeg[r1] > 0.0f) ? 1.0f : 0.0f;
        #pragma unroll
        for (int nt = 0; nt < 4; nt++) {
            int cb = wc * 32 + nt * 8 + t * 2;
            float v0 = fmaxf(acc[mt][nt][0] + b20[nt] + f0 * cv0[nt], 0.0f);
            float v1 = fmaxf(acc[mt][nt][1] + b21[nt] + f0 * cv1[nt], 0.0f);
            float v2 = fmaxf(acc[mt][nt][2] + b20[nt] + f1 * cv0[nt], 0.0f);
            float v3 = fmaxf(acc[mt][nt][3] + b21[nt] + f1 * cv1[nt], 0.0f);
            if (r0 < NN) {
                __half2 hh = __floats2half2_rn(v0, v1);
                *(unsigned*)(g_hx + (size_t)r0 * DD + cb) = *(unsigned*)&hh;
                cs[nt * 2] += v0;     cq[nt * 2] += v0 * v0;
                cs[nt * 2 + 1] += v1; cq[nt * 2 + 1] += v1 * v1;
            }
            if (r1 < NN) {
                __half2 hh = __floats2half2_rn(v2, v3);
                *(unsigned*)(g_hx + (size_t)r1 * DD + cb) = *(unsigned*)&hh;
                cs[nt * 2] += v2;     cq[nt * 2] += v2 * v2;
                cs[nt * 2 + 1] += v3; cq[nt * 2 + 1] += v3 * v3;
            }
        }
    }

    __syncthreads();
    float* smf = (float*)smh;
    if (tid < 256) smf[tid] = 0.0f;
    __syncthreads();
    #pragma unroll
    for (int nt = 0; nt < 4; nt++) {
        int cb = wc * 32 + nt * 8 + t * 2;
        atomicAdd(&smf[cb], cs[nt * 2]);
        atomicAdd(&smf[cb + 1], cs[nt * 2 + 1]);
        atomicAdd(&smf[128 + cb], cq[nt * 2]);
        atomicAdd(&smf[128 + cb + 1], cq[nt * 2 + 1]);
    }
    __syncthreads();
    if (tid < 128) {
        atomicAdd(&g_sum[tid], smf[tid]);
        atomicAdd(&g_sumsq[tid], smf[128 + tid]);
    }
}

// ---------------- BN finalize (+ zero stats for next layer) ----------------
__global__ void k_bn_finalize(const float* __restrict__ gamma,
                              const float* __restrict__ beta) {
    int c = threadIdx.x;
    if (c < DD) {
        float m = g_sum[c] * (1.0f / (float)NN);
        float v = g_sumsq[c] * (1.0f / (float)NN) - m * m;
        v = fmaxf(v, 0.0f);
        float sc = gamma[c] * rsqrtf(v + EPSV);
        g_scale[c] = sc;
        g_shift[c] = beta[c] - m * sc;
        g_sum[c] = 0.0f;
        g_sumsq[c] = 0.0f;
    }
}

// ---------------- output layer (BN of last layer folded in) ----------------
__global__ void k_pq(const float* __restrict__ wlo, const float* __restrict__ wro) {
    int warp = (blockIdx.x * blockDim.x + threadIdx.x) >> 5;
    int lane = threadIdx.x & 31;
    if (warp >= NN) return;
    uint2 hraw = ((const uint2*)(g_hx + (size_t)warp * DD))[lane];
    float2 v0 = __half22float2(*(__half2*)&hraw.x);
    float2 v1 = __half22float2(*(__half2*)&hraw.y);
    float4 s4 = ((const float4*)g_scale)[lane];
    float4 h4 = ((const float4*)g_shift)[lane];
    float4 hv;
    hv.x = s4.x * v0.x + h4.x;
    hv.y = s4.y * v0.y + h4.y;
    hv.z = s4.z * v1.x + h4.z;
    hv.w = s4.w * v1.y + h4.w;
    float4 wl = ((const float4*)wlo)[lane];
    float4 wrv = ((const float4*)wro)[lane];
    float p = hv.x * wl.x + hv.y * wl.y + hv.z * wl.z + hv.w * wl.w;
    float q = hv.x * wrv.x + hv.y * wrv.y + hv.z * wrv.z + hv.w * wrv.w;
    #pragma unroll
    for (int o = 16; o > 0; o >>= 1) {
        p += __shfl_down_sync(0xffffffffu, p, o);
        q += __shfl_down_sync(0xffffffffu, q, o);
    }
    if (lane == 0) { g_p[warp] = p; g_q[warp] = q; }
}

__global__ void k_final(const float* __restrict__ b_out, float* __restrict__ out) {
    int n = blockIdx.x * blockDim.x + threadIdx.x;
    if (n >= NN) return;
    int s = g_rowptr[n], e = g_rowptr[n + 1];
    float acc = 0.0f;
    for (int j = s; j < e; j++) acc += g_p[g_col[j]];
    float z = acc * g_invdeg[n] + g_q[n] + b_out[0];
    out[n] = 1.0f / (1.0f + expf(-z));
}

// ---------------- host ----------------
extern "C" void kernel_launch(void* const* d_in, const int* in_sizes, int n_in,
                              void* d_out, int out_size) {
    const float* x     = (const float*)d_in[0];
    const void*  ei    = d_in[1];
    const float* Wl    = (const float*)d_in[2];
    const float* Wr    = (const float*)d_in[3];
    const float* b     = (const float*)d_in[4];
    const float* gamma = (const float*)d_in[5];
    const float* beta  = (const float*)d_in[6];
    const float* Wlo   = (const float*)d_in[7];
    const float* Wro   = (const float*)d_in[8];
    const float* bo    = (const float*)d_in[9];
    float* out = (float*)d_out;

    cudaFuncSetAttribute(k_mma, cudaFuncAttributeMaxDynamicSharedMemorySize, SMEM_MMA);

    // device addresses of scratch buffers
    __half* wbh;
    float *b2, *cv;
    cudaGetSymbolAddress((void**)&wbh, g_wbh);
    cudaGetSymbolAddress((void**)&b2, g_b2);
    cudaGetSymbolAddress((void**)&cv, g_cv);

    // edge dtype detect; CSR build; fp16 mirror of x; layer-0 weight fold
    k_detect<<<1, 256>>>((const unsigned int*)ei);
    k_zero_deg<<<(NN + 255) / 256, 256>>>();
    k_hist<<<(EE + 255) / 256, 256>>>(ei);
    k_x2h<<<(NN * (DD / 4) + 255) / 256, 256>>>(x);
    k_wprep<<<257, 128>>>(Wl, Wr, b, 0, wbh, b2, cv);
    k_scan_a<<<NCH, 1024>>>();
    k_scan_b<<<1, 32>>>();
    k_scan_c<<<(NN + 255) / 256, 256>>>();
    k_prep<<<(NN + 255) / 256, 256>>>();
    k_scatter<<<(EE + 255) / 256, 256>>>(ei);

    // hidden layers (activations live in g_hx fp16, updated in place)
    for (int l = 0; l < LL; l++) {
        int slot = l & 1;
        k_agg<<<(NN + 7) / 8, 256>>>();
        k_mma<<<(NN + 127) / 128, 256, SMEM_MMA>>>(wbh + (size_t)slot * 128 * 256,
                                                   b2 + slot * DD,
                                                   cv + slot * DD);
        k_bn_finalize<<<1, 128>>>(gamma + l * DD, beta + l * DD);
        if (l + 1 < LL) {
            int ns = (l + 1) & 1;
            k_wprep<<<257, 128>>>(Wl + (l + 1) * DD * DD, Wr + (l + 1) * DD * DD,
                                  b + (l + 1) * DD, 1,
                                  wbh + (size_t)ns * 128 * 256,
                                  b2 + ns * DD, cv + ns * DD);
        }
    }

    // output layer (BN of last hidden layer applied inline in k_pq)
    k_pq<<<(NN + 3) / 4, 128>>>(Wlo, Wro);
    k_final<<<(NN + 255) / 256, 256>>>(bo, out);
    (void)in_sizes; (void)n_in; (void)out_size;
}

// round 14
// speedup vs baseline: 1.2209x; 1.0086x over previous
#include <cuda_runtime.h>
#include <cuda_fp16.h>
#include <math.h>

#define NN 100000
#define EE 1600000
#define DD 128
#define LL 3
#define EPSV 1e-5f
#define NCH ((NN + 1023) / 1024)   // scan chunks = 98

// ---------------- scratch (static __device__, no allocation) ----------------
__device__ int    g_is64;
__device__ int    g_deg[NN];
__device__ int    g_rowptr[NN + 1];
__device__ int    g_cursor[NN];
__device__ int    g_col[EE];
__device__ int    g_bsum[128];
__device__ int    g_boff[128];
__device__ float  g_invdeg[NN];
__device__ __half g_hx[NN * DD];       // fp16 activations (raw pre-BN), in-place
__device__ __half g_mh[NN * DD];       // fp16 neighbor mean
__device__ __half g_wbh[2][128 * 256]; // folded fp16 weights, TRANSPOSED [n][k]
__device__ float  g_b2[2][DD];         // bias + sh^T Wr
__device__ float  g_cv[2][DD];         // sh^T Wl (applied x [deg>0])
__device__ float  g_sum[DD];
__device__ float  g_sumsq[DD];
__device__ float  g_scale[DD];
__device__ float  g_shift[DD];
__device__ float  g_p[NN];
__device__ float  g_q[NN];

// ---------------- helpers ----------------
__device__ __forceinline__ void mma_f16(float* c, const unsigned* a, const unsigned* b) {
    asm volatile(
        "mma.sync.aligned.m16n8k16.row.col.f32.f16.f16.f32 "
        "{%0,%1,%2,%3}, {%4,%5,%6,%7}, {%8,%9}, {%0,%1,%2,%3};"
        : "+f"(c[0]), "+f"(c[1]), "+f"(c[2]), "+f"(c[3])
        : "r"(a[0]), "r"(a[1]), "r"(a[2]), "r"(a[3]), "r"(b[0]), "r"(b[1]));
}

__device__ __forceinline__ void cpa16(unsigned saddr, const void* g, int srcsz) {
    asm volatile("cp.async.cg.shared.global [%0], [%1], 16, %2;\n"
                 :: "r"(saddr), "l"(g), "r"(srcsz));
}
__device__ __forceinline__ void cpa_commit() {
    asm volatile("cp.async.commit_group;\n" ::: "memory");
}
template <int N> __device__ __forceinline__ void cpa_wait() {
    asm volatile("cp.async.wait_group %0;\n" :: "n"(N) : "memory");
}

__device__ __forceinline__ int dec_idx(const void* ei, long long pos, int is64) {
    int v = is64 ? (int)((const long long*)ei)[pos] : ((const int*)ei)[pos];
    return min(max(v, 0), NN - 1);
}

// ---------------- dtype detect ----------------
__global__ void k_detect(const unsigned int* __restrict__ w) {
    __shared__ int nz;
    if (threadIdx.x == 0) nz = 0;
    __syncthreads();
    if (w[threadIdx.x * 2 + 1] != 0u) atomicOr(&nz, 1);
    __syncthreads();
    if (threadIdx.x == 0) g_is64 = nz ? 0 : 1;
}

__global__ void k_zero_deg() {
    int i = blockIdx.x * blockDim.x + threadIdx.x;
    if (i < NN) g_deg[i] = 0;
}

__global__ void k_hist(const void* __restrict__ ei) {
    int e = blockIdx.x * blockDim.x + threadIdx.x;
    if (e >= EE) return;
    int d = dec_idx(ei, (long long)EE + e, g_is64);
    atomicAdd(&g_deg[d], 1);
}

// ---------------- CSR scan ----------------
__global__ void k_scan_a() {
    __shared__ int swarp[32];
    int tid = threadIdx.x;
    int i = blockIdx.x * 1024 + tid;
    int v = (i < NN) ? g_deg[i] : 0;
    int lane = tid & 31, w = tid >> 5;
    int x = v;
    #pragma unroll
    for (int o = 1; o < 32; o <<= 1) {
        int y = __shfl_up_sync(0xffffffffu, x, o);
        if (lane >= o) x += y;
    }
    if (lane == 31) swarp[w] = x;
    __syncthreads();
    if (w == 0) {
        int y = swarp[lane];
        #pragma unroll
        for (int o = 1; o < 32; o <<= 1) {
            int z = __shfl_up_sync(0xffffffffu, y, o);
            if (lane >= o) y += z;
        }
        swarp[lane] = y;
    }
    __syncthreads();
    int add = (w > 0) ? swarp[w - 1] : 0;
    x += add;
    if (i < NN) g_rowptr[i + 1] = x;
    if (tid == 1023) g_bsum[blockIdx.x] = x;
}

__global__ void k_scan_b() {
    if (threadIdx.x == 0) {
        int r = 0;
        for (int b = 0; b < NCH; b++) { g_boff[b] = r; r += g_bsum[b]; }
    }
}

__global__ void k_scan_c() {
    int i = blockIdx.x * blockDim.x + threadIdx.x;
    if (i < NN) {
        g_rowptr[i + 1] += g_boff[i >> 10];
        if (i == 0) g_rowptr[0] = 0;
    }
}

// prep + zero first-layer BN stats
__global__ void k_prep() {
    int i = blockIdx.x * blockDim.x + threadIdx.x;
    if (i < NN) {
        g_cursor[i] = g_rowptr[i];
        int d = g_deg[i];
        g_invdeg[i] = (d > 0) ? (1.0f / (float)d) : 0.0f;
    }
    if (i < DD) { g_sum[i] = 0.0f; g_sumsq[i] = 0.0f; }
}

__global__ void k_scatter(const void* __restrict__ ei) {
    int e = blockIdx.x * blockDim.x + threadIdx.x;
    if (e < EE) {
        int is64 = g_is64;
        int s = dec_idx(ei, e, is64);
        int d = dec_idx(ei, (long long)EE + e, is64);
        int pos = atomicAdd(&g_cursor[d], 1);
        g_col[pos] = s;
    }
}

// ---------------- x -> fp16 mirror ----------------
__global__ void k_x2h(const float* __restrict__ x) {
    int i4 = blockIdx.x * blockDim.x + threadIdx.x;   // float4 index
    if (i4 < NN * (DD / 4)) {
        float4 v = __ldg(&((const float4*)x)[i4]);
        __half2 h0 = __floats2half2_rn(v.x, v.y);
        __half2 h1 = __floats2half2_rn(v.z, v.w);
        uint2 o;
        o.x = *(unsigned*)&h0;
        o.y = *(unsigned*)&h1;
        ((uint2*)g_hx)[i4] = o;
    }
}

// --------- weight fold: Wt[n][k] = fp16(s_k * [Wl;Wr][k][n]), bias', cvec ---
__global__ void k_wprep(const float* __restrict__ Wl, const float* __restrict__ Wr,
                        const float* __restrict__ bias, int useScale,
                        __half* __restrict__ wout, float* __restrict__ b2,
                        float* __restrict__ cv) {
    int blk = blockIdx.x, j = threadIdx.x;   // j = n (output col)
    if (blk < 256) {
        int k = (blk < 128) ? blk : blk - 128;
        float s = useScale ? g_scale[k] : 1.0f;
        const float* W = (blk < 128) ? Wl : Wr;
        wout[j * 256 + blk] = __float2half(s * __ldg(&W[k * DD + j]));
    } else {
        float sb = 0.0f, sc = 0.0f;
        if (useScale) {
            for (int k = 0; k < DD; k++) {
                float sh = g_shift[k];
                sc += sh * __ldg(&Wl[k * DD + j]);
                sb += sh * __ldg(&Wr[k * DD + j]);
            }
        }
        b2[j] = __ldg(&bias[j]) + sb;
        cv[j] = sc;
    }
}

// ------- aggregation: warp per node, fp16 gather, fp32 acc, fp16 store ------
__global__ void __launch_bounds__(256) k_agg() {
    int n = blockIdx.x * 8 + (threadIdx.x >> 5);
    if (n >= NN) return;
    int lane = threadIdx.x & 31;
    int s = g_rowptr[n], e = g_rowptr[n + 1];
    float4 acc = make_float4(0.f, 0.f, 0.f, 0.f);
    const __half* hx = g_hx;
    int j = s;
    for (; j + 3 < e; j += 4) {
        int c0 = g_col[j], c1 = g_col[j + 1], c2 = g_col[j + 2], c3 = g_col[j + 3];
        uint2 a = __ldg(((const uint2*)(hx + (size_t)c0 * DD)) + lane);
        uint2 b = __ldg(((const uint2*)(hx + (size_t)c1 * DD)) + lane);
        uint2 c = __ldg(((const uint2*)(hx + (size_t)c2 * DD)) + lane);
        uint2 d = __ldg(((const uint2*)(hx + (size_t)c3 * DD)) + lane);
        float2 a0 = __half22float2(*(__half2*)&a.x), a1 = __half22float2(*(__half2*)&a.y);
        float2 b0 = __half22float2(*(__half2*)&b.x), b1 = __half22float2(*(__half2*)&b.y);
        float2 c0f = __half22float2(*(__half2*)&c.x), c1f = __half22float2(*(__half2*)&c.y);
        float2 d0 = __half22float2(*(__half2*)&d.x), d1 = __half22float2(*(__half2*)&d.y);
        acc.x += (a0.x + b0.x) + (c0f.x + d0.x);
        acc.y += (a0.y + b0.y) + (c0f.y + d0.y);
        acc.z += (a1.x + b1.x) + (c1f.x + d1.x);
        acc.w += (a1.y + b1.y) + (c1f.y + d1.y);
    }
    for (; j < e; j++) {
        uint2 a = __ldg(((const uint2*)(hx + (size_t)g_col[j] * DD)) + lane);
        float2 a0 = __half22float2(*(__half2*)&a.x), a1 = __half22float2(*(__half2*)&a.y);
        acc.x += a0.x; acc.y += a0.y; acc.z += a1.x; acc.w += a1.y;
    }
    float iv = g_invdeg[n];
    __half2 h0 = __floats2half2_rn(acc.x * iv, acc.y * iv);
    __half2 h1 = __floats2half2_rn(acc.z * iv, acc.w * iv);
    uint2 o;
    o.x = *(unsigned*)&h0;
    o.y = *(unsigned*)&h1;
    ((uint2*)(g_mh + (size_t)n * DD))[lane] = o;
}

// ---------------- fp16 MMA: persistent CTAs, W resident in smem -------------
// smem layout: [ W 128x264h (67584B) | A buf0 (10240B) | A buf1 (10240B) |
//               stats 1024B ]  = 89088 B  -> 2 CTAs/SM.
// W staged ONCE per CTA (full 256-half rows = 32 segs of 16B); per tile only
// A chunks are cp.async'd (R8 skeleton: stage-next-before-wait).
#define SAKH 40
#define WSTR 264                            // halves
#define W_BYTES (128 * WSTR * 2)            // 67584
#define A_BUF_BYTES (128 * SAKH * 2)        // 10240
#define STATS_OFF_H ((W_BYTES + 2 * A_BUF_BYTES) / 2)   // halves offset
#define SMEM_MMA (W_BYTES + 2 * A_BUF_BYTES + 1024)     // 89088

__global__ void __launch_bounds__(256, 2) k_mma(
    const __half* __restrict__ wbuf, const float* __restrict__ bias2,
    const float* __restrict__ cvec, int nTiles)
{
    extern __shared__ __half smh[];
    unsigned smbase = (unsigned)__cvta_generic_to_shared(smh);

    int tid = threadIdx.x;
    int wid = tid >> 5;
    int lane = tid & 31;
    int wr_ = wid >> 2;
    int wc = wid & 3;
    int g = lane >> 2;
    int t = lane & 3;

    // ---- stage full W once: 128 n-rows x 32 segs of 16B (4096 cp.asyncs) ----
    #pragma unroll
    for (int it = 0; it < 16; it++) {
        int i = tid + it * 256;              // 0..4095
        int r = i >> 5, seg = i & 31;
        const __half* gp = wbuf + (size_t)r * 256 + seg * 8;
        cpa16(smbase + (unsigned)(r * WSTR + seg * 8) * 2u, gp, 16);
    }
    cpa_commit();

    const __half* sW = smh;                  // resident weights
    unsigned aBase0 = smbase + W_BYTES;      // A double buffers

    auto stageA = [&](int rowBase, int ck, int b) {
        unsigned base = aBase0 + (unsigned)b * A_BUF_BYTES;
        #pragma unroll
        for (int it = 0; it < 2; it++) {
            int i = tid + it * 256;          // 0..511: 128 rows x 4 segs of 16B
            int r = i >> 2, seg = i & 3;
            int row = rowBase + r;
            int ok = (row < NN) ? 16 : 0;
            int crow = min(row, NN - 1);
            const __half* gp = (ck < 4)
                ? (g_mh + (size_t)crow * DD + ck * 32 + seg * 8)
                : (g_hx + (size_t)crow * DD + (ck - 4) * 32 + seg * 8);
            cpa16(base + (unsigned)(r * SAKH + seg * 8) * 2u, gp, ok);
        }
    };

    for (int tile = blockIdx.x; tile < nTiles; tile += gridDim.x) {
        int rowBase = tile * 128;

        float acc[4][4][4];
        #pragma unroll
        for (int mt = 0; mt < 4; mt++)
            #pragma unroll
            for (int nt = 0; nt < 4; nt++)
                #pragma unroll
                for (int q = 0; q < 4; q++) acc[mt][nt][q] = 0.0f;

        stageA(rowBase, 0, 0);
        cpa_commit();

        #pragma unroll 1
        for (int ck = 0; ck < 8; ck++) {
            if (ck < 7) {
                stageA(rowBase, ck + 1, (ck + 1) & 1);  // stage BEFORE wait
                cpa_commit();
                cpa_wait<1>();
            } else {
                cpa_wait<0>();
            }
            __syncthreads();

            const __half* bA = smh + W_BYTES / 2 + (ck & 1) * (A_BUF_BYTES / 2);

            #pragma unroll
            for (int kk = 0; kk < 2; kk++) {
                unsigned a[4][4];
                #pragma unroll
                for (int mt = 0; mt < 4; mt++) {
                    const __half* pa = bA + (wr_ * 64 + mt * 16 + g) * SAKH + kk * 16 + 2 * t;
                    a[mt][0] = *(const unsigned*)(pa);
                    a[mt][1] = *(const unsigned*)(pa + 8 * SAKH);
                    a[mt][2] = *(const unsigned*)(pa + 8);
                    a[mt][3] = *(const unsigned*)(pa + 8 * SAKH + 8);
                }
                unsigned b[4][2];
                #pragma unroll
                for (int nt = 0; nt < 4; nt++) {
                    const __half* pb = sW + (wc * 32 + nt * 8 + g) * WSTR
                                          + ck * 32 + kk * 16 + 2 * t;
                    b[nt][0] = *(const unsigned*)(pb);
                    b[nt][1] = *(const unsigned*)(pb + 8);
                }
                #pragma unroll
                for (int mt = 0; mt < 4; mt++)
                    #pragma unroll
                    for (int nt = 0; nt < 4; nt++)
                        mma_f16(acc[mt][nt], a[mt], b[nt]);
            }
            __syncthreads();
        }

        // ---- epilogue: bias' + flag*cvec + relu + fp16 in-place + stats ----
        float b20[4], b21[4], cv0[4], cv1[4];
        #pragma unroll
        for (int nt = 0; nt < 4; nt++) {
            int cb = wc * 32 + nt * 8 + t * 2;
            b20[nt] = __ldg(&bias2[cb]);
            b21[nt] = __ldg(&bias2[cb + 1]);
            cv0[nt] = __ldg(&cvec[cb]);
            cv1[nt] = __ldg(&cvec[cb + 1]);
        }

        float cs[8], cq[8];
        #pragma unroll
        for (int q = 0; q < 8; q++) { cs[q] = 0.f; cq[q] = 0.f; }

        #pragma unroll
        for (int mt = 0; mt < 4; mt++) {
            int r0 = rowBase + wr_ * 64 + mt * 16 + g;
            int r1 = r0 + 8;
            float f0 = (r0 < NN && g_invdeg[r0] > 0.0f) ? 1.0f : 0.0f;
            float f1 = (r1 < NN && g_invdeg[r1] > 0.0f) ? 1.0f : 0.0f;
            #pragma unroll
            for (int nt = 0; nt < 4; nt++) {
                int cb = wc * 32 + nt * 8 + t * 2;
                float v0 = fmaxf(acc[mt][nt][0] + b20[nt] + f0 * cv0[nt], 0.0f);
                float v1 = fmaxf(acc[mt][nt][1] + b21[nt] + f0 * cv1[nt], 0.0f);
                float v2 = fmaxf(acc[mt][nt][2] + b20[nt] + f1 * cv0[nt], 0.0f);
                float v3 = fmaxf(acc[mt][nt][3] + b21[nt] + f1 * cv1[nt], 0.0f);
                if (r0 < NN) {
                    __half2 hh = __floats2half2_rn(v0, v1);
                    *(unsigned*)(g_hx + (size_t)r0 * DD + cb) = *(unsigned*)&hh;
                    cs[nt * 2] += v0;     cq[nt * 2] += v0 * v0;
                    cs[nt * 2 + 1] += v1; cq[nt * 2 + 1] += v1 * v1;
                }
                if (r1 < NN) {
                    __half2 hh = __floats2half2_rn(v2, v3);
                    *(unsigned*)(g_hx + (size_t)r1 * DD + cb) = *(unsigned*)&hh;
                    cs[nt * 2] += v2;     cq[nt * 2] += v2 * v2;
                    cs[nt * 2 + 1] += v3; cq[nt * 2 + 1] += v3 * v3;
                }
            }
        }

        // stats scratch lives in its own region (does NOT alias W or A bufs)
        float* smf = (float*)(smh + STATS_OFF_H);
        __syncthreads();
        if (tid < 256) smf[tid] = 0.0f;
        __syncthreads();
        #pragma unroll
        for (int nt = 0; nt < 4; nt++) {
            int cb = wc * 32 + nt * 8 + t * 2;
            atomicAdd(&smf[cb], cs[nt * 2]);
            atomicAdd(&smf[cb + 1], cs[nt * 2 + 1]);
            atomicAdd(&smf[128 + cb], cq[nt * 2]);
            atomicAdd(&smf[128 + cb + 1], cq[nt * 2 + 1]);
        }
        __syncthreads();
        if (tid < 128) {
            atomicAdd(&g_sum[tid], smf[tid]);
            atomicAdd(&g_sumsq[tid], smf[128 + tid]);
        }
        __syncthreads();
    }
}

// ---------------- BN finalize (+ zero stats for next layer) ----------------
__global__ void k_bn_finalize(const float* __restrict__ gamma,
                              const float* __restrict__ beta) {
    int c = threadIdx.x;
    if (c < DD) {
        float m = g_sum[c] * (1.0f / (float)NN);
        float v = g_sumsq[c] * (1.0f / (float)NN) - m * m;
        v = fmaxf(v, 0.0f);
        float sc = gamma[c] * rsqrtf(v + EPSV);
        g_scale[c] = sc;
        g_shift[c] = beta[c] - m * sc;
        g_sum[c] = 0.0f;
        g_sumsq[c] = 0.0f;
    }
}

// ---------------- output layer (BN of last layer folded in) ----------------
__global__ void k_pq(const float* __restrict__ wlo, const float* __restrict__ wro) {
    int warp = (blockIdx.x * blockDim.x + threadIdx.x) >> 5;
    int lane = threadIdx.x & 31;
    if (warp >= NN) return;
    uint2 hraw = ((const uint2*)(g_hx + (size_t)warp * DD))[lane];
    float2 v0 = __half22float2(*(__half2*)&hraw.x);
    float2 v1 = __half22float2(*(__half2*)&hraw.y);
    float4 s4 = ((const float4*)g_scale)[lane];
    float4 h4 = ((const float4*)g_shift)[lane];
    float4 hv;
    hv.x = s4.x * v0.x + h4.x;
    hv.y = s4.y * v0.y + h4.y;
    hv.z = s4.z * v1.x + h4.z;
    hv.w = s4.w * v1.y + h4.w;
    float4 wl = ((const float4*)wlo)[lane];
    float4 wrv = ((const float4*)wro)[lane];
    float p = hv.x * wl.x + hv.y * wl.y + hv.z * wl.z + hv.w * wl.w;
    float q = hv.x * wrv.x + hv.y * wrv.y + hv.z * wrv.z + hv.w * wrv.w;
    #pragma unroll
    for (int o = 16; o > 0; o >>= 1) {
        p += __shfl_down_sync(0xffffffffu, p, o);
        q += __shfl_down_sync(0xffffffffu, q, o);
    }
    if (lane == 0) { g_p[warp] = p; g_q[warp] = q; }
}

__global__ void k_final(const float* __restrict__ b_out, float* __restrict__ out) {
    int n = blockIdx.x * blockDim.x + threadIdx.x;
    if (n >= NN) return;
    int s = g_rowptr[n], e = g_rowptr[n + 1];
    float acc = 0.0f;
    for (int j = s; j < e; j++) acc += g_p[g_col[j]];
    float z = acc * g_invdeg[n] + g_q[n] + b_out[0];
    out[n] = 1.0f / (1.0f + expf(-z));
}

// ---------------- host ----------------
extern "C" void kernel_launch(void* const* d_in, const int* in_sizes, int n_in,
                              void* d_out, int out_size) {
    const float* x     = (const float*)d_in[0];
    const void*  ei    = d_in[1];
    const float* Wl    = (const float*)d_in[2];
    const float* Wr    = (const float*)d_in[3];
    const float* b     = (const float*)d_in[4];
    const float* gamma = (const float*)d_in[5];
    const float* beta  = (const float*)d_in[6];
    const float* Wlo   = (const float*)d_in[7];
    const float* Wro   = (const float*)d_in[8];
    const float* bo    = (const float*)d_in[9];
    float* out = (float*)d_out;

    cudaFuncSetAttribute(k_mma, cudaFuncAttributeMaxDynamicSharedMemorySize, SMEM_MMA);

    // persistent grid sizing for k_mma
    int dev = 0;
    cudaGetDevice(&dev);
    int sms = 0;
    cudaDeviceGetAttribute(&sms, cudaDevAttrMultiProcessorCount, dev);
    int nbk = 0;
    cudaOccupancyMaxActiveBlocksPerMultiprocessor(&nbk, k_mma, 256, SMEM_MMA);
    if (nbk < 1) nbk = 1;
    if (nbk > 2) nbk = 2;
    const int nTiles = (NN + 127) / 128;   // 782
    int mmaGrid = sms * nbk;
    if (mmaGrid > nTiles) mmaGrid = nTiles;

    // device addresses of scratch buffers
    __half* wbh;
    float *b2, *cv;
    cudaGetSymbolAddress((void**)&wbh, g_wbh);
    cudaGetSymbolAddress((void**)&b2, g_b2);
    cudaGetSymbolAddress((void**)&cv, g_cv);

    // edge dtype detect; CSR build; fp16 mirror of x; layer-0 weight fold
    k_detect<<<1, 256>>>((const unsigned int*)ei);
    k_zero_deg<<<(NN + 255) / 256, 256>>>();
    k_hist<<<(EE + 255) / 256, 256>>>(ei);
    k_x2h<<<(NN * (DD / 4) + 255) / 256, 256>>>(x);
    k_wprep<<<257, 128>>>(Wl, Wr, b, 0, wbh, b2, cv);
    k_scan_a<<<NCH, 1024>>>();
    k_scan_b<<<1, 32>>>();
    k_scan_c<<<(NN + 255) / 256, 256>>>();
    k_prep<<<(NN + 255) / 256, 256>>>();
    k_scatter<<<(EE + 255) / 256, 256>>>(ei);

    // hidden layers (activations live in g_hx fp16, updated in place)
    for (int l = 0; l < LL; l++) {
        int slot = l & 1;
        k_agg<<<(NN + 7) / 8, 256>>>();
        k_mma<<<mmaGrid, 256, SMEM_MMA>>>(wbh + (size_t)slot * 128 * 256,
                                          b2 + slot * DD,
                                          cv + slot * DD, nTiles);
        k_bn_finalize<<<1, 128>>>(gamma + l * DD, beta + l * DD);
        if (l + 1 < LL) {
            int ns = (l + 1) & 1;
            k_wprep<<<257, 128>>>(Wl + (l + 1) * DD * DD, Wr + (l + 1) * DD * DD,
                                  b + (l + 1) * DD, 1,
                                  wbh + (size_t)ns * 128 * 256,
                                  b2 + ns * DD, cv + ns * DD);
        }
    }

    // output layer (BN of last hidden layer applied inline in k_pq)
    k_pq<<<(NN + 3) / 4, 128>>>(Wlo, Wro);
    k_final<<<(NN + 255) / 256, 256>>>(bo, out);
    (void)in_sizes; (void)n_in; (void)out_size;
}

// round 15
// speedup vs baseline: 1.2410x; 1.0165x over previous
#include <cuda_runtime.h>
#include <cuda_fp16.h>
#include <math.h>

#define NN 100000
#define EE 1600000
#define DD 128
#define LL 3
#define EPSV 1e-5f
#define NCH ((NN + 1023) / 1024)   // scan chunks = 98
#define HISTB ((EE + 255) / 256)           // 6250
#define X2HB ((NN * (DD / 4) + 255) / 256) // 12500

// ---------------- scratch (static __device__, no allocation) ----------------
__device__ int    g_is64;
__device__ int    g_deg[NN];
__device__ int    g_rowptr[NN + 1];
__device__ int    g_cursor[NN];
__device__ int    g_col[EE];
__device__ int    g_bsum[128];
__device__ int    g_boff[128];
__device__ float  g_invdeg[NN];
__device__ __half g_hx[NN * DD];       // fp16 activations (raw pre-BN), in-place
__device__ __half g_mh[NN * DD];       // fp16 neighbor mean
__device__ __half g_wbh[2][128 * 256]; // folded fp16 weights, TRANSPOSED [n][k]
__device__ float  g_b2[2][DD];         // bias + sh^T Wr
__device__ float  g_cv[2][DD];         // sh^T Wl (applied x [deg>0])
__device__ float  g_sum[DD];
__device__ float  g_sumsq[DD];
__device__ float  g_scale[DD];
__device__ float  g_shift[DD];
__device__ float  g_p[NN];
__device__ float  g_q[NN];

// ---------------- helpers ----------------
__device__ __forceinline__ void mma_f16(float* c, const unsigned* a, const unsigned* b) {
    asm volatile(
        "mma.sync.aligned.m16n8k16.row.col.f32.f16.f16.f32 "
        "{%0,%1,%2,%3}, {%4,%5,%6,%7}, {%8,%9}, {%0,%1,%2,%3};"
        : "+f"(c[0]), "+f"(c[1]), "+f"(c[2]), "+f"(c[3])
        : "r"(a[0]), "r"(a[1]), "r"(a[2]), "r"(a[3]), "r"(b[0]), "r"(b[1]));
}

__device__ __forceinline__ void cpa16(unsigned saddr, const void* g, int srcsz) {
    asm volatile("cp.async.cg.shared.global [%0], [%1], 16, %2;\n"
                 :: "r"(saddr), "l"(g), "r"(srcsz));
}
__device__ __forceinline__ void cpa_commit() {
    asm volatile("cp.async.commit_group;\n" ::: "memory");
}
template <int N> __device__ __forceinline__ void cpa_wait() {
    asm volatile("cp.async.wait_group %0;\n" :: "n"(N) : "memory");
}

__device__ __forceinline__ int dec_idx(const void* ei, long long pos, int is64) {
    int v = is64 ? (int)((const long long*)ei)[pos] : ((const int*)ei)[pos];
    return min(max(v, 0), NN - 1);
}

// ---------------- init: zero degrees + dtype detect (block 0) ---------------
__global__ void k_init(const unsigned int* __restrict__ w) {
    int i = blockIdx.x * blockDim.x + threadIdx.x;
    if (i < NN) g_deg[i] = 0;
    if (blockIdx.x == 0) {
        __shared__ int nz;
        if (threadIdx.x == 0) nz = 0;
        __syncthreads();
        if (w[threadIdx.x * 2 + 1] != 0u) atomicOr(&nz, 1);
        __syncthreads();
        if (threadIdx.x == 0) g_is64 = nz ? 0 : 1;
    }
}

// ---------------- fused: degree histogram + x -> fp16 mirror ----------------
__global__ void k_hist_x2h(const void* __restrict__ ei, const float* __restrict__ x) {
    if (blockIdx.x < HISTB) {
        int e = blockIdx.x * 256 + threadIdx.x;
        if (e < EE) {
            int d = dec_idx(ei, (long long)EE + e, g_is64);
            atomicAdd(&g_deg[d], 1);
        }
    } else {
        int i4 = (blockIdx.x - HISTB) * 256 + threadIdx.x;
        if (i4 < NN * (DD / 4)) {
            float4 v = __ldg(&((const float4*)x)[i4]);
            __half2 h0 = __floats2half2_rn(v.x, v.y);
            __half2 h1 = __floats2half2_rn(v.z, v.w);
            uint2 o;
            o.x = *(unsigned*)&h0;
            o.y = *(unsigned*)&h1;
            ((uint2*)g_hx)[i4] = o;
        }
    }
}

// ---------------- CSR scan ----------------
__global__ void k_scan_a() {
    __shared__ int swarp[32];
    int tid = threadIdx.x;
    int i = blockIdx.x * 1024 + tid;
    int v = (i < NN) ? g_deg[i] : 0;
    int lane = tid & 31, w = tid >> 5;
    int x = v;
    #pragma unroll
    for (int o = 1; o < 32; o <<= 1) {
        int y = __shfl_up_sync(0xffffffffu, x, o);
        if (lane >= o) x += y;
    }
    if (lane == 31) swarp[w] = x;
    __syncthreads();
    if (w == 0) {
        int y = swarp[lane];
        #pragma unroll
        for (int o = 1; o < 32; o <<= 1) {
            int z = __shfl_up_sync(0xffffffffu, y, o);
            if (lane >= o) y += z;
        }
        swarp[lane] = y;
    }
    __syncthreads();
    int add = (w > 0) ? swarp[w - 1] : 0;
    x += add;
    if (i < NN) g_rowptr[i + 1] = x;
    if (tid == 1023) g_bsum[blockIdx.x] = x;
}

__global__ void k_scan_b() {
    if (threadIdx.x == 0) {
        int r = 0;
        for (int b = 0; b < NCH; b++) { g_boff[b] = r; r += g_bsum[b]; }
    }
}

__global__ void k_scan_c() {
    int i = blockIdx.x * blockDim.x + threadIdx.x;
    if (i < NN) {
        g_rowptr[i + 1] += g_boff[i >> 10];
        if (i == 0) g_rowptr[0] = 0;
    }
}

// prep + zero first-layer BN stats
__global__ void k_prep() {
    int i = blockIdx.x * blockDim.x + threadIdx.x;
    if (i < NN) {
        g_cursor[i] = g_rowptr[i];
        int d = g_deg[i];
        g_invdeg[i] = (d > 0) ? (1.0f / (float)d) : 0.0f;
    }
    if (i < DD) { g_sum[i] = 0.0f; g_sumsq[i] = 0.0f; }
}

__global__ void k_scatter(const void* __restrict__ ei) {
    int e = blockIdx.x * blockDim.x + threadIdx.x;
    if (e < EE) {
        int is64 = g_is64;
        int s = dec_idx(ei, e, is64);
        int d = dec_idx(ei, (long long)EE + e, is64);
        int pos = atomicAdd(&g_cursor[d], 1);
        g_col[pos] = s;
    }
}

// --------- weight fold: Wt[n][k] = fp16(s_k * [Wl;Wr][k][n]), bias', cvec ---
__global__ void k_wprep(const float* __restrict__ Wl, const float* __restrict__ Wr,
                        const float* __restrict__ bias, int useScale,
                        __half* __restrict__ wout, float* __restrict__ b2,
                        float* __restrict__ cv) {
    int blk = blockIdx.x, j = threadIdx.x;   // j = n (output col)
    if (blk < 256) {
        int k = (blk < 128) ? blk : blk - 128;
        float s = useScale ? g_scale[k] : 1.0f;
        const float* W = (blk < 128) ? Wl : Wr;
        wout[j * 256 + blk] = __float2half(s * __ldg(&W[k * DD + j]));
    } else {
        float sb = 0.0f, sc = 0.0f;
        if (useScale) {
            for (int k = 0; k < DD; k++) {
                float sh = g_shift[k];
                sc += sh * __ldg(&Wl[k * DD + j]);
                sb += sh * __ldg(&Wr[k * DD + j]);
            }
        }
        b2[j] = __ldg(&bias[j]) + sb;
        cv[j] = sc;
    }
}

// ------- aggregation: warp per node, fp16 gather, fp32 acc, fp16 store ------
__global__ void __launch_bounds__(256) k_agg() {
    int n = blockIdx.x * 8 + (threadIdx.x >> 5);
    if (n >= NN) return;
    int lane = threadIdx.x & 31;
    int s = g_rowptr[n], e = g_rowptr[n + 1];
    float4 acc = make_float4(0.f, 0.f, 0.f, 0.f);
    const __half* hx = g_hx;
    int j = s;
    for (; j + 3 < e; j += 4) {
        int c0 = g_col[j], c1 = g_col[j + 1], c2 = g_col[j + 2], c3 = g_col[j + 3];
        uint2 a = __ldg(((const uint2*)(hx + (size_t)c0 * DD)) + lane);
        uint2 b = __ldg(((const uint2*)(hx + (size_t)c1 * DD)) + lane);
        uint2 c = __ldg(((const uint2*)(hx + (size_t)c2 * DD)) + lane);
        uint2 d = __ldg(((const uint2*)(hx + (size_t)c3 * DD)) + lane);
        float2 a0 = __half22float2(*(__half2*)&a.x), a1 = __half22float2(*(__half2*)&a.y);
        float2 b0 = __half22float2(*(__half2*)&b.x), b1 = __half22float2(*(__half2*)&b.y);
        float2 c0f = __half22float2(*(__half2*)&c.x), c1f = __half22float2(*(__half2*)&c.y);
        float2 d0 = __half22float2(*(__half2*)&d.x), d1 = __half22float2(*(__half2*)&d.y);
        acc.x += (a0.x + b0.x) + (c0f.x + d0.x);
        acc.y += (a0.y + b0.y) + (c0f.y + d0.y);
        acc.z += (a1.x + b1.x) + (c1f.x + d1.x);
        acc.w += (a1.y + b1.y) + (c1f.y + d1.y);
    }
    for (; j < e; j++) {
        uint2 a = __ldg(((const uint2*)(hx + (size_t)g_col[j] * DD)) + lane);
        float2 a0 = __half22float2(*(__half2*)&a.x), a1 = __half22float2(*(__half2*)&a.y);
        acc.x += a0.x; acc.y += a0.y; acc.z += a1.x; acc.w += a1.y;
    }
    float iv = g_invdeg[n];
    __half2 h0 = __floats2half2_rn(acc.x * iv, acc.y * iv);
    __half2 h1 = __floats2half2_rn(acc.z * iv, acc.w * iv);
    uint2 o;
    o.x = *(unsigned*)&h0;
    o.y = *(unsigned*)&h1;
    ((uint2*)(g_mh + (size_t)n * DD))[lane] = o;
}

// ---------------- fp16 MMA: persistent CTAs, W resident in smem -------------
// smem layout: [ W 128x264h (67584B) | A buf0 (10240B) | A buf1 (10240B) |
//               stats 1024B ]  = 89088 B  -> 2 CTAs/SM.
// W staged ONCE per CTA (full 256-half rows = 32 segs of 16B); per tile only
// A chunks are cp.async'd (R8 skeleton: stage-next-before-wait).
#define SAKH 40
#define WSTR 264                            // halves
#define W_BYTES (128 * WSTR * 2)            // 67584
#define A_BUF_BYTES (128 * SAKH * 2)        // 10240
#define STATS_OFF_H ((W_BYTES + 2 * A_BUF_BYTES) / 2)   // halves offset
#define SMEM_MMA (W_BYTES + 2 * A_BUF_BYTES + 1024)     // 89088

__global__ void __launch_bounds__(256, 2) k_mma(
    const __half* __restrict__ wbuf, const float* __restrict__ bias2,
    const float* __restrict__ cvec, int nTiles)
{
    extern __shared__ __half smh[];
    unsigned smbase = (unsigned)__cvta_generic_to_shared(smh);

    int tid = threadIdx.x;
    int wid = tid >> 5;
    int lane = tid & 31;
    int wr_ = wid >> 2;
    int wc = wid & 3;
    int g = lane >> 2;
    int t = lane & 3;

    // ---- stage full W once: 128 n-rows x 32 segs of 16B (4096 cp.asyncs) ----
    #pragma unroll
    for (int it = 0; it < 16; it++) {
        int i = tid + it * 256;              // 0..4095
        int r = i >> 5, seg = i & 31;
        const __half* gp = wbuf + (size_t)r * 256 + seg * 8;
        cpa16(smbase + (unsigned)(r * WSTR + seg * 8) * 2u, gp, 16);
    }
    cpa_commit();

    const __half* sW = smh;                  // resident weights
    unsigned aBase0 = smbase + W_BYTES;      // A double buffers

    auto stageA = [&](int rowBase, int ck, int b) {
        unsigned base = aBase0 + (unsigned)b * A_BUF_BYTES;
        #pragma unroll
        for (int it = 0; it < 2; it++) {
            int i = tid + it * 256;          // 0..511: 128 rows x 4 segs of 16B
            int r = i >> 2, seg = i & 3;
            int row = rowBase + r;
            int ok = (row < NN) ? 16 : 0;
            int crow = min(row, NN - 1);
            const __half* gp = (ck < 4)
                ? (g_mh + (size_t)crow * DD + ck * 32 + seg * 8)
                : (g_hx + (size_t)crow * DD + (ck - 4) * 32 + seg * 8);
            cpa16(base + (unsigned)(r * SAKH + seg * 8) * 2u, gp, ok);
        }
    };

    for (int tile = blockIdx.x; tile < nTiles; tile += gridDim.x) {
        int rowBase = tile * 128;

        float acc[4][4][4];
        #pragma unroll
        for (int mt = 0; mt < 4; mt++)
            #pragma unroll
            for (int nt = 0; nt < 4; nt++)
                #pragma unroll
                for (int q = 0; q < 4; q++) acc[mt][nt][q] = 0.0f;

        stageA(rowBase, 0, 0);
        cpa_commit();

        #pragma unroll 1
        for (int ck = 0; ck < 8; ck++) {
            if (ck < 7) {
                stageA(rowBase, ck + 1, (ck + 1) & 1);  // stage BEFORE wait
                cpa_commit();
                cpa_wait<1>();
            } else {
                cpa_wait<0>();
            }
            __syncthreads();

            const __half* bA = smh + W_BYTES / 2 + (ck & 1) * (A_BUF_BYTES / 2);

            #pragma unroll
            for (int kk = 0; kk < 2; kk++) {
                unsigned a[4][4];
                #pragma unroll
                for (int mt = 0; mt < 4; mt++) {
                    const __half* pa = bA + (wr_ * 64 + mt * 16 + g) * SAKH + kk * 16 + 2 * t;
                    a[mt][0] = *(const unsigned*)(pa);
                    a[mt][1] = *(const unsigned*)(pa + 8 * SAKH);
                    a[mt][2] = *(const unsigned*)(pa + 8);
                    a[mt][3] = *(const unsigned*)(pa + 8 * SAKH + 8);
                }
                unsigned b[4][2];
                #pragma unroll
                for (int nt = 0; nt < 4; nt++) {
                    const __half* pb = sW + (wc * 32 + nt * 8 + g) * WSTR
                                          + ck * 32 + kk * 16 + 2 * t;
                    b[nt][0] = *(const unsigned*)(pb);
                    b[nt][1] = *(const unsigned*)(pb + 8);
                }
                #pragma unroll
                for (int mt = 0; mt < 4; mt++)
                    #pragma unroll
                    for (int nt = 0; nt < 4; nt++)
                        mma_f16(acc[mt][nt], a[mt], b[nt]);
            }
            __syncthreads();
        }

        // ---- epilogue: bias' + flag*cvec + relu + fp16 in-place + stats ----
        float b20[4], b21[4], cv0[4], cv1[4];
        #pragma unroll
        for (int nt = 0; nt < 4; nt++) {
            int cb = wc * 32 + nt * 8 + t * 2;
            b20[nt] = __ldg(&bias2[cb]);
            b21[nt] = __ldg(&bias2[cb + 1]);
            cv0[nt] = __ldg(&cvec[cb]);
            cv1[nt] = __ldg(&cvec[cb + 1]);
        }

        float cs[8], cq[8];
        #pragma unroll
        for (int q = 0; q < 8; q++) { cs[q] = 0.f; cq[q] = 0.f; }

        #pragma unroll
        for (int mt = 0; mt < 4; mt++) {
            int r0 = rowBase + wr_ * 64 + mt * 16 + g;
            int r1 = r0 + 8;
            float f0 = (r0 < NN && g_invdeg[r0] > 0.0f) ? 1.0f : 0.0f;
            float f1 = (r1 < NN && g_invdeg[r1] > 0.0f) ? 1.0f : 0.0f;
            #pragma unroll
            for (int nt = 0; nt < 4; nt++) {
                int cb = wc * 32 + nt * 8 + t * 2;
                float v0 = fmaxf(acc[mt][nt][0] + b20[nt] + f0 * cv0[nt], 0.0f);
                float v1 = fmaxf(acc[mt][nt][1] + b21[nt] + f0 * cv1[nt], 0.0f);
                float v2 = fmaxf(acc[mt][nt][2] + b20[nt] + f1 * cv0[nt], 0.0f);
                float v3 = fmaxf(acc[mt][nt][3] + b21[nt] + f1 * cv1[nt], 0.0f);
                if (r0 < NN) {
                    __half2 hh = __floats2half2_rn(v0, v1);
                    *(unsigned*)(g_hx + (size_t)r0 * DD + cb) = *(unsigned*)&hh;
                    cs[nt * 2] += v0;     cq[nt * 2] += v0 * v0;
                    cs[nt * 2 + 1] += v1; cq[nt * 2 + 1] += v1 * v1;
                }
                if (r1 < NN) {
                    __half2 hh = __floats2half2_rn(v2, v3);
                    *(unsigned*)(g_hx + (size_t)r1 * DD + cb) = *(unsigned*)&hh;
                    cs[nt * 2] += v2;     cq[nt * 2] += v2 * v2;
                    cs[nt * 2 + 1] += v3; cq[nt * 2 + 1] += v3 * v3;
                }
            }
        }

        // stats scratch lives in its own region (does NOT alias W or A bufs)
        float* smf = (float*)(smh + STATS_OFF_H);
        __syncthreads();
        if (tid < 256) smf[tid] = 0.0f;
        __syncthreads();
        #pragma unroll
        for (int nt = 0; nt < 4; nt++) {
            int cb = wc * 32 + nt * 8 + t * 2;
            atomicAdd(&smf[cb], cs[nt * 2]);
            atomicAdd(&smf[cb + 1], cs[nt * 2 + 1]);
            atomicAdd(&smf[128 + cb], cq[nt * 2]);
            atomicAdd(&smf[128 + cb + 1], cq[nt * 2 + 1]);
        }
        __syncthreads();
        if (tid < 128) {
            atomicAdd(&g_sum[tid], smf[tid]);
            atomicAdd(&g_sumsq[tid], smf[128 + tid]);
        }
        __syncthreads();
    }
}

// ---------------- BN finalize (+ zero stats for next layer) ----------------
__global__ void k_bn_finalize(const float* __restrict__ gamma,
                              const float* __restrict__ beta) {
    int c = threadIdx.x;
    if (c < DD) {
        float m = g_sum[c] * (1.0f / (float)NN);
        float v = g_sumsq[c] * (1.0f / (float)NN) - m * m;
        v = fmaxf(v, 0.0f);
        float sc = gamma[c] * rsqrtf(v + EPSV);
        g_scale[c] = sc;
        g_shift[c] = beta[c] - m * sc;
        g_sum[c] = 0.0f;
        g_sumsq[c] = 0.0f;
    }
}

// ---------------- output layer (BN of last layer folded in) ----------------
__global__ void k_pq(const float* __restrict__ wlo, const float* __restrict__ wro) {
    int warp = (blockIdx.x * blockDim.x + threadIdx.x) >> 5;
    int lane = threadIdx.x & 31;
    if (warp >= NN) return;
    uint2 hraw = ((const uint2*)(g_hx + (size_t)warp * DD))[lane];
    float2 v0 = __half22float2(*(__half2*)&hraw.x);
    float2 v1 = __half22float2(*(__half2*)&hraw.y);
    float4 s4 = ((const float4*)g_scale)[lane];
    float4 h4 = ((const float4*)g_shift)[lane];
    float4 hv;
    hv.x = s4.x * v0.x + h4.x;
    hv.y = s4.y * v0.y + h4.y;
    hv.z = s4.z * v1.x + h4.z;
    hv.w = s4.w * v1.y + h4.w;
    float4 wl = ((const float4*)wlo)[lane];
    float4 wrv = ((const float4*)wro)[lane];
    float p = hv.x * wl.x + hv.y * wl.y + hv.z * wl.z + hv.w * wl.w;
    float q = hv.x * wrv.x + hv.y * wrv.y + hv.z * wrv.z + hv.w * wrv.w;
    #pragma unroll
    for (int o = 16; o > 0; o >>= 1) {
        p += __shfl_down_sync(0xffffffffu, p, o);
        q += __shfl_down_sync(0xffffffffu, q, o);
    }
    if (lane == 0) { g_p[warp] = p; g_q[warp] = q; }
}

__global__ void k_final(const float* __restrict__ b_out, float* __restrict__ out) {
    int n = blockIdx.x * blockDim.x + threadIdx.x;
    if (n >= NN) return;
    int s = g_rowptr[n], e = g_rowptr[n + 1];
    float acc = 0.0f;
    for (int j = s; j < e; j++) acc += g_p[g_col[j]];
    float z = acc * g_invdeg[n] + g_q[n] + b_out[0];
    out[n] = 1.0f / (1.0f + expf(-z));
}

// ---------------- host ----------------
extern "C" void kernel_launch(void* const* d_in, const int* in_sizes, int n_in,
                              void* d_out, int out_size) {
    const float* x     = (const float*)d_in[0];
    const void*  ei    = d_in[1];
    const float* Wl    = (const float*)d_in[2];
    const float* Wr    = (const float*)d_in[3];
    const float* b     = (const float*)d_in[4];
    const float* gamma = (const float*)d_in[5];
    const float* beta  = (const float*)d_in[6];
    const float* Wlo   = (const float*)d_in[7];
    const float* Wro   = (const float*)d_in[8];
    const float* bo    = (const float*)d_in[9];
    float* out = (float*)d_out;

    cudaFuncSetAttribute(k_mma, cudaFuncAttributeMaxDynamicSharedMemorySize, SMEM_MMA);

    // persistent grid sizing for k_mma
    int dev = 0;
    cudaGetDevice(&dev);
    int sms = 0;
    cudaDeviceGetAttribute(&sms, cudaDevAttrMultiProcessorCount, dev);
    int nbk = 0;
    cudaOccupancyMaxActiveBlocksPerMultiprocessor(&nbk, k_mma, 256, SMEM_MMA);
    if (nbk < 1) nbk = 1;
    if (nbk > 2) nbk = 2;
    const int nTiles = (NN + 127) / 128;   // 782
    int mmaGrid = sms * nbk;
    if (mmaGrid > nTiles) mmaGrid = nTiles;

    // device addresses of scratch buffers
    __half* wbh;
    float *b2, *cv;
    cudaGetSymbolAddress((void**)&wbh, g_wbh);
    cudaGetSymbolAddress((void**)&b2, g_b2);
    cudaGetSymbolAddress((void**)&cv, g_cv);

    // preamble: init (zero deg + detect), fused hist+x2h, layer-0 fold, CSR
    k_init<<<(NN + 255) / 256, 256>>>((const unsigned int*)ei);
    k_hist_x2h<<<HISTB + X2HB, 256>>>(ei, x);
    k_wprep<<<257, 128>>>(Wl, Wr, b, 0, wbh, b2, cv);
    k_scan_a<<<NCH, 1024>>>();
    k_scan_b<<<1, 32>>>();
    k_scan_c<<<(NN + 255) / 256, 256>>>();
    k_prep<<<(NN + 255) / 256, 256>>>();
    k_scatter<<<(EE + 255) / 256, 256>>>(ei);

    // hidden layers (activations live in g_hx fp16, updated in place)
    for (int l = 0; l < LL; l++) {
        int slot = l & 1;
        k_agg<<<(NN + 7) / 8, 256>>>();
        k_mma<<<mmaGrid, 256, SMEM_MMA>>>(wbh + (size_t)slot * 128 * 256,
                                          b2 + slot * DD,
                                          cv + slot * DD, nTiles);
        k_bn_finalize<<<1, 128>>>(gamma + l * DD, beta + l * DD);
        if (l + 1 < LL) {
            int ns = (l + 1) & 1;
            k_wprep<<<257, 128>>>(Wl + (l + 1) * DD * DD, Wr + (l + 1) * DD * DD,
                                  b + (l + 1) * DD, 1,
                                  wbh + (size_t)ns * 128 * 256,
                                  b2 + ns * DD, cv + ns * DD);
        }
    }

    // output layer (BN of last hidden layer applied inline in k_pq)
    k_pq<<<(NN + 3) / 4, 128>>>(Wlo, Wro);
    k_final<<<(NN + 255) / 256, 256>>>(bo, out);
    (void)in_sizes; (void)n_in; (void)out_size;
}